// round 5
// baseline (speedup 1.0000x reference)
#include <cuda_runtime.h>
#include <cstdint>

#define NROI      256
#define NCH       256
#define NPTS      7
#define HP        8
#define H0F       200
#define W0F       336
#define IMG_W     1344.0f
#define IMG_H     800.0f
#define CCHUNK    16          // channels per block

// ---------------------------------------------------------------------------
// Warp-contiguous gather pooler, single fused launch.
//
// Thread layout: lane = one output x (warp covers 32 CONSECUTIVE x in one
// row), so the 4 bilinear gathers per channel have warp footprints of only a
// few 128B lines (adjacent lanes sample texels ~0.5-2.5 apart). This kills
// the L1 wavefront explosion of the quad layout (was 80.9% L1-bound).
//
// Each thread: compute its 4 gather offsets + 4 mask-fused weights ONCE,
// then stream CCHUNK channels: 4 LDG + 4 FMA + 1 coalesced STG.32 each,
// channel loop unrolled x4 => 16 loads in flight.
//
// Work decomposition (grid.x = 48, grid.y = NROI):
//   bx in [0,16):  output0 (WP=32): 256 thr = 32 x * 8 y, chunk = bx
//   bx in [16,48): output1 (WP=64): 256 thr = 64 x * 4 y, idx = bx-16,
//                  chunk = idx/2, y-half = idx%2
// Blocks whose ROI belongs to the other pooler stream float4 zeros.
// ---------------------------------------------------------------------------

template <int WP, int PID, int YROWS>
__device__ __forceinline__ void pool_body(
    int chunk, int yblk, int n,
    const float* __restrict__ f0, const float* __restrict__ f1,
    const float* __restrict__ f2, const float* __restrict__ f3,
    float* __restrict__ outp,
    const float* sp, int s_lvl, int s_pid, int s_img) {

    const int x  = threadIdx.x % WP;
    const int y  = yblk * YROWS + threadIdx.x / WP;
    const int c0 = chunk * CCHUNK;

    if (s_pid != PID) {
        // Zero the block's region: CCHUNK channels x YROWS rows x WP floats
        // = 4096 floats = 1024 float4, 4 per thread. Per channel the YROWS*WP
        // span is contiguous.
        constexpr int F4_PER_CH = YROWS * WP / 4;   // 64
        const float4 z = make_float4(0.f, 0.f, 0.f, 0.f);
#pragma unroll
        for (int t = 0; t < 4; t++) {
            int idx = t * 256 + threadIdx.x;
            int c   = idx / F4_PER_CH;
            int off = idx % F4_PER_CH;
            float4* zp = (float4*)(outp +
                (((size_t)n * NCH + c0 + c) * HP + yblk * YROWS) * WP) + off;
            *zp = z;
        }
        return;
    }

    int H, W;
    const float* feat;
    switch (s_lvl) {
        case 0:  H = H0F;     W = W0F;     feat = f0; break;
        case 1:  H = H0F / 2; W = W0F / 2; feat = f1; break;
        case 2:  H = H0F / 4; W = W0F / 4; feat = f2; break;
        default: H = H0F / 8; W = W0F / 8; feat = f3; break;
    }
    const size_t HW = (size_t)H * W;
    const float* p = feat + ((size_t)s_img * NCH + c0) * HW;
    float* op = outp + (((size_t)n * NCH + c0) * HP + y) * WP + x;

    // --- per-thread grid sample (once) ---
    const float v    = (y + 0.5f) * (1.0f / HP);
    const float invW = 1.0f / IMG_W, invH = 1.0f / IMG_H;

    float u = (x + 0.5f) * ((float)(NPTS - 1) / (float)WP);
    int i0 = (int)floorf(u);
    i0 = max(0, min(i0, NPTS - 2));
    float f = u - (float)i0;
    int j0 = 13 - i0, j1 = 12 - i0;

    float tx = (sp[2 * i0]     * (1.0f - f) + sp[2 * (i0 + 1)]     * f) * invW;
    float ty = (sp[2 * i0 + 1] * (1.0f - f) + sp[2 * (i0 + 1) + 1] * f) * invH;
    float bx = (sp[2 * j0]     * (1.0f - f) + sp[2 * j1]     * f) * invW;
    float by = (sp[2 * j0 + 1] * (1.0f - f) + sp[2 * j1 + 1] * f) * invH;

    float gx = tx * (1.0f - v) + bx * v;
    float gy = ty * (1.0f - v) + by * v;

    float xf = gx * (float)W - 0.5f;
    float yf = gy * (float)H - 0.5f;
    float x0f = floorf(xf), y0f = floorf(yf);
    float wx = xf - x0f, wy = yf - y0f;
    int x0 = (int)x0f, y0i = (int)y0f;
    int x1 = x0 + 1,   y1 = y0i + 1;

    int x0c = min(max(x0, 0), W - 1), x1c = min(max(x1, 0), W - 1);
    int y0c = min(max(y0i, 0), H - 1), y1c = min(max(y1, 0), H - 1);
    float m00 = ((x0 >= 0) & (x0 < W) & (y0i >= 0) & (y0i < H)) ? 1.0f : 0.0f;
    float m10 = ((x1 >= 0) & (x1 < W) & (y0i >= 0) & (y0i < H)) ? 1.0f : 0.0f;
    float m01 = ((x0 >= 0) & (x0 < W) & (y1 >= 0) & (y1 < H)) ? 1.0f : 0.0f;
    float m11 = ((x1 >= 0) & (x1 < W) & (y1 >= 0) & (y1 < H)) ? 1.0f : 0.0f;

    const float w00 = m00 * (1.0f - wx) * (1.0f - wy);
    const float w10 = m10 * wx          * (1.0f - wy);
    const float w01 = m01 * (1.0f - wx) * wy;
    const float w11 = m11 * wx          * wy;

    const int o00 = y0c * W + x0c;
    const int o10 = y0c * W + x1c;
    const int o01 = y1c * W + x0c;
    const int o11 = y1c * W + x1c;

    constexpr size_t OST = (size_t)HP * WP;   // output channel stride

    // --- channel stream, unrolled x4 -> 16 loads in flight ---
#pragma unroll 4
    for (int c = 0; c < CCHUNK; c++) {
        float v00 = __ldg(p + o00);
        float v10 = __ldg(p + o10);
        float v01 = __ldg(p + o01);
        float v11 = __ldg(p + o11);
        float r = v00 * w00 + v10 * w10 + v01 * w01 + v11 * w11;
        op[(size_t)c * OST] = r;
        p += HW;
    }
}

__global__ void __launch_bounds__(256, 4)
fused_pool_kernel(const float* __restrict__ f0, const float* __restrict__ f1,
                  const float* __restrict__ f2, const float* __restrict__ f3,
                  const float* __restrict__ polys, const int* __restrict__ img_ids,
                  const int* __restrict__ lens, float* __restrict__ out) {
    const int n = blockIdx.y;

    __shared__ float sp[2 * NPTS * 2];
    __shared__ int s_lvl, s_pid, s_img;

    if (threadIdx.x < 2 * NPTS * 2)
        sp[threadIdx.x] = polys[(size_t)n * (2 * NPTS * 2) + threadIdx.x];
    __syncthreads();

    if (threadIdx.x == 0) {
        float minx = sp[0], maxx = sp[0], miny = sp[1], maxy = sp[1];
#pragma unroll
        for (int i = 1; i < 2 * NPTS; i++) {
            float px = sp[2 * i], py = sp[2 * i + 1];
            minx = fminf(minx, px); maxx = fmaxf(maxx, px);
            miny = fminf(miny, py); maxy = fmaxf(maxy, py);
        }
        float s  = sqrtf((maxx - minx) * (maxy - miny));
        float vv = 4.0f + log2f(s / 224.0f + 1e-6f);
        float fl = fminf(fmaxf(floorf(vv), 2.0f), 5.0f);
        s_lvl = (int)fl - 2;
        s_pid = (lens[n] > 8) ? 1 : 0;
        s_img = img_ids[n];
    }
    __syncthreads();

    constexpr int CHUNKS = NCH / CCHUNK;   // 16

    if (blockIdx.x < CHUNKS) {
        // Output 0: (N, C, 8, 32), pooler 0. 256 thr = 32 x * 8 y.
        pool_body<32, 0, 8>(blockIdx.x, 0, n, f0, f1, f2, f3,
                            out, sp, s_lvl, s_pid, s_img);
    } else {
        // Output 1: (N, C, 8, 64), pooler 1. 256 thr = 64 x * 4 y, 2 y-halves.
        const int idx = blockIdx.x - CHUNKS;
        float* out1 = out + (size_t)NROI * NCH * HP * 32;
        pool_body<64, 1, 4>(idx >> 1, idx & 1, n, f0, f1, f2, f3,
                            out1, sp, s_lvl, s_pid, s_img);
    }
}

extern "C" void kernel_launch(void* const* d_in, const int* in_sizes, int n_in,
                              void* d_out, int out_size) {
    const float* f0     = (const float*)d_in[0];
    const float* f1     = (const float*)d_in[1];
    const float* f2     = (const float*)d_in[2];
    const float* f3     = (const float*)d_in[3];
    const float* polys  = (const float*)d_in[4];
    const int*   imgids = (const int*)  d_in[5];
    const int*   lens   = (const int*)  d_in[6];
    float* out = (float*)d_out;

    const int N = in_sizes[4] / (2 * NPTS * 2);   // 256

    dim3 grid(3 * (NCH / CCHUNK), N);             // 48 x 256
    fused_pool_kernel<<<grid, 256>>>(f0, f1, f2, f3, polys, imgids, lens, out);
}

// round 6
// speedup vs baseline: 1.9113x; 1.9113x over previous
#include <cuda_runtime.h>
#include <cstdint>

#define NROI      256
#define NCH       256
#define NPTS      7
#define HP        8
#define H0F       200
#define W0F       336
#define IMG_W     1344.0f
#define IMG_H     800.0f
#define CCHUNK    32          // channels per block

// ---------------------------------------------------------------------------
// Lane-contiguous pooler, deep-MLP version, single fused launch, no smem.
//
// - lane = one output x (warp covers 32 consecutive x) -> warp gather
//   footprint is a few 128B lines per tap (L1-friendly, proven in R5).
// - CCHUNK=32 channels per block, channel loop unrolled x8 -> up to 32
//   independent LDGs in flight per thread (covers DRAM/L2 latency).
// - NO __syncthreads / smem: every thread computes the ROI meta from
//   __ldg broadcast reads (uniform across block; removes the serial
//   thread-0 preamble and 2 barriers per block).
//
// Grid (24, NROI):
//   bx in [0,8):   output0 (WP=32): 256 thr = 32 x * 8 y, chunk = bx
//   bx in [8,24):  output1 (WP=64): 256 thr = 64 x * 4 y, idx = bx-8,
//                  chunk = idx>>1, y-half = idx&1
// ---------------------------------------------------------------------------

template <int WP, int PID, int YROWS>
__device__ __forceinline__ void pool_body(
    int chunk, int yblk, int n,
    const float* __restrict__ f0, const float* __restrict__ f1,
    const float* __restrict__ f2, const float* __restrict__ f3,
    float* __restrict__ outp, const float* __restrict__ pp,
    int s_lvl, int s_pid, int s_img) {

    const int x  = threadIdx.x % WP;
    const int y  = yblk * YROWS + threadIdx.x / WP;
    const int c0 = chunk * CCHUNK;

    if (s_pid != PID) {
        // Zero region: CCHUNK channels x YROWS x WP = 8192 floats = 2048 f4.
        constexpr int F4_PER_CH = YROWS * WP / 4;   // 64
        const float4 z = make_float4(0.f, 0.f, 0.f, 0.f);
#pragma unroll
        for (int t = 0; t < CCHUNK * F4_PER_CH / 256; t++) {   // 8
            int idx = t * 256 + threadIdx.x;
            int c   = idx / F4_PER_CH;
            int off = idx % F4_PER_CH;
            float4* zp = (float4*)(outp +
                (((size_t)n * NCH + c0 + c) * HP + yblk * YROWS) * WP) + off;
            *zp = z;
        }
        return;
    }

    int H, W;
    const float* feat;
    switch (s_lvl) {
        case 0:  H = H0F;     W = W0F;     feat = f0; break;
        case 1:  H = H0F / 2; W = W0F / 2; feat = f1; break;
        case 2:  H = H0F / 4; W = W0F / 4; feat = f2; break;
        default: H = H0F / 8; W = W0F / 8; feat = f3; break;
    }
    const size_t HW = (size_t)H * W;
    const float* p = feat + ((size_t)s_img * NCH + c0) * HW;
    float* op = outp + (((size_t)n * NCH + c0) * HP + y) * WP + x;

    // --- per-thread grid sample (once) ---
    const float v    = (y + 0.5f) * (1.0f / HP);
    const float invW = 1.0f / IMG_W, invH = 1.0f / IMG_H;

    float u = (x + 0.5f) * ((float)(NPTS - 1) / (float)WP);
    int i0 = (int)floorf(u);
    i0 = max(0, min(i0, NPTS - 2));
    float f = u - (float)i0;
    int j0 = 13 - i0, j1 = 12 - i0;

    float tx = (__ldg(pp + 2*i0)       * (1.0f - f) + __ldg(pp + 2*(i0+1))     * f) * invW;
    float ty = (__ldg(pp + 2*i0 + 1)   * (1.0f - f) + __ldg(pp + 2*(i0+1) + 1) * f) * invH;
    float bx = (__ldg(pp + 2*j0)       * (1.0f - f) + __ldg(pp + 2*j1)         * f) * invW;
    float by = (__ldg(pp + 2*j0 + 1)   * (1.0f - f) + __ldg(pp + 2*j1 + 1)     * f) * invH;

    float gx = tx * (1.0f - v) + bx * v;
    float gy = ty * (1.0f - v) + by * v;

    float xf = gx * (float)W - 0.5f;
    float yf = gy * (float)H - 0.5f;
    float x0f = floorf(xf), y0f = floorf(yf);
    float wx = xf - x0f, wy = yf - y0f;
    int x0 = (int)x0f, y0i = (int)y0f;
    int x1 = x0 + 1,   y1 = y0i + 1;

    int x0c = min(max(x0, 0), W - 1), x1c = min(max(x1, 0), W - 1);
    int y0c = min(max(y0i, 0), H - 1), y1c = min(max(y1, 0), H - 1);
    float m00 = ((x0 >= 0) & (x0 < W) & (y0i >= 0) & (y0i < H)) ? 1.0f : 0.0f;
    float m10 = ((x1 >= 0) & (x1 < W) & (y0i >= 0) & (y0i < H)) ? 1.0f : 0.0f;
    float m01 = ((x0 >= 0) & (x0 < W) & (y1 >= 0) & (y1 < H)) ? 1.0f : 0.0f;
    float m11 = ((x1 >= 0) & (x1 < W) & (y1 >= 0) & (y1 < H)) ? 1.0f : 0.0f;

    const float w00 = m00 * (1.0f - wx) * (1.0f - wy);
    const float w10 = m10 * wx          * (1.0f - wy);
    const float w01 = m01 * (1.0f - wx) * wy;
    const float w11 = m11 * wx          * wy;

    const int o00 = y0c * W + x0c;
    const int o10 = y0c * W + x1c;
    const int o01 = y1c * W + x0c;
    const int o11 = y1c * W + x1c;

    constexpr size_t OST = (size_t)HP * WP;   // output channel stride

    // --- channel stream, unrolled x8 -> 32 loads batched ---
#pragma unroll 8
    for (int c = 0; c < CCHUNK; c++) {
        float v00 = __ldg(p + o00);
        float v10 = __ldg(p + o10);
        float v01 = __ldg(p + o01);
        float v11 = __ldg(p + o11);
        float r = v00 * w00 + v10 * w10 + v01 * w01 + v11 * w11;
        op[(size_t)c * OST] = r;
        p += HW;
    }
}

__global__ void __launch_bounds__(256, 4)
fused_pool_kernel(const float* __restrict__ f0, const float* __restrict__ f1,
                  const float* __restrict__ f2, const float* __restrict__ f3,
                  const float* __restrict__ polys, const int* __restrict__ img_ids,
                  const int* __restrict__ lens, float* __restrict__ out) {
    const int n = blockIdx.y;
    const float* pp = polys + (size_t)n * (2 * NPTS * 2);

    // --- per-thread uniform meta (broadcast __ldg; no smem, no barriers) ---
    float minx = __ldg(pp + 0), maxx = minx;
    float miny = __ldg(pp + 1), maxy = miny;
#pragma unroll
    for (int i = 1; i < 2 * NPTS; i++) {
        float px = __ldg(pp + 2 * i), py = __ldg(pp + 2 * i + 1);
        minx = fminf(minx, px); maxx = fmaxf(maxx, px);
        miny = fminf(miny, py); maxy = fmaxf(maxy, py);
    }
    float s  = sqrtf((maxx - minx) * (maxy - miny));
    float vv = 4.0f + log2f(s / 224.0f + 1e-6f);
    float fl = fminf(fmaxf(floorf(vv), 2.0f), 5.0f);
    const int s_lvl = (int)fl - 2;
    const int s_pid = (__ldg(lens + n) > 8) ? 1 : 0;
    const int s_img = __ldg(img_ids + n);

    constexpr int CHUNKS = NCH / CCHUNK;   // 8

    if (blockIdx.x < CHUNKS) {
        // Output 0: (N, C, 8, 32), pooler 0. 256 thr = 32 x * 8 y.
        pool_body<32, 0, 8>(blockIdx.x, 0, n, f0, f1, f2, f3,
                            out, pp, s_lvl, s_pid, s_img);
    } else {
        // Output 1: (N, C, 8, 64), pooler 1. 256 thr = 64 x * 4 y, 2 halves.
        const int idx = blockIdx.x - CHUNKS;
        float* out1 = out + (size_t)NROI * NCH * HP * 32;
        pool_body<64, 1, 4>(idx >> 1, idx & 1, n, f0, f1, f2, f3,
                            out1, pp, s_lvl, s_pid, s_img);
    }
}

extern "C" void kernel_launch(void* const* d_in, const int* in_sizes, int n_in,
                              void* d_out, int out_size) {
    const float* f0     = (const float*)d_in[0];
    const float* f1     = (const float*)d_in[1];
    const float* f2     = (const float*)d_in[2];
    const float* f3     = (const float*)d_in[3];
    const float* polys  = (const float*)d_in[4];
    const int*   imgids = (const int*)  d_in[5];
    const int*   lens   = (const int*)  d_in[6];
    float* out = (float*)d_out;

    const int N = in_sizes[4] / (2 * NPTS * 2);   // 256

    dim3 grid(3 * (NCH / CCHUNK), N);             // 24 x 256
    fused_pool_kernel<<<grid, 256>>>(f0, f1, f2, f3, polys, imgids, lens, out);
}

// round 7
// speedup vs baseline: 1.9233x; 1.0063x over previous
#include <cuda_runtime.h>
#include <cstdint>

#define NROI      256
#define NCH       256
#define NPTS      7
#define HP        8
#define H0F       200
#define W0F       336
#define IMG_W     1344.0f
#define IMG_H     800.0f
#define CCHUNK    32          // channels per block

// ---------------------------------------------------------------------------
// Lane-contiguous pooler, deep-MLP, streaming stores, single fused launch.
//
// - lane = one output x (warp covers 32 consecutive x) -> warp gather
//   footprint is a few 128B lines per tap.
// - CCHUNK=32 channels per block, channel loop unrolled x8 for load batching.
// - No smem / no barriers: ROI meta recomputed per thread from broadcast
//   __ldg reads (uniform).
// - __stcs (evict-first) on all output stores: output is write-once, keep
//   L2 for the feature gather working set.
// - __launch_bounds__(256, 5): target 62.5% occupancy (51-reg budget).
//
// Grid (24, NROI):
//   bx in [0,8):   output0 (WP=32): 256 thr = 32 x * 8 y, chunk = bx
//   bx in [8,24):  output1 (WP=64): 256 thr = 64 x * 4 y, idx = bx-8,
//                  chunk = idx>>1, y-half = idx&1
// ---------------------------------------------------------------------------

template <int WP, int PID, int YROWS>
__device__ __forceinline__ void pool_body(
    int chunk, int yblk, int n,
    const float* __restrict__ f0, const float* __restrict__ f1,
    const float* __restrict__ f2, const float* __restrict__ f3,
    float* __restrict__ outp, const float* __restrict__ pp,
    int s_lvl, int s_pid, int s_img) {

    const int x  = threadIdx.x % WP;
    const int y  = yblk * YROWS + threadIdx.x / WP;
    const int c0 = chunk * CCHUNK;

    if (s_pid != PID) {
        // Zero region: CCHUNK channels x YROWS x WP = 8192 floats = 2048 f4.
        constexpr int F4_PER_CH = YROWS * WP / 4;   // 64
        const float4 z = make_float4(0.f, 0.f, 0.f, 0.f);
#pragma unroll
        for (int t = 0; t < CCHUNK * F4_PER_CH / 256; t++) {   // 8
            int idx = t * 256 + threadIdx.x;
            int c   = idx / F4_PER_CH;
            int off = idx % F4_PER_CH;
            float4* zp = (float4*)(outp +
                (((size_t)n * NCH + c0 + c) * HP + yblk * YROWS) * WP) + off;
            __stcs(zp, z);
        }
        return;
    }

    int H, W;
    const float* feat;
    switch (s_lvl) {
        case 0:  H = H0F;     W = W0F;     feat = f0; break;
        case 1:  H = H0F / 2; W = W0F / 2; feat = f1; break;
        case 2:  H = H0F / 4; W = W0F / 4; feat = f2; break;
        default: H = H0F / 8; W = W0F / 8; feat = f3; break;
    }
    const size_t HW = (size_t)H * W;
    const float* p = feat + ((size_t)s_img * NCH + c0) * HW;
    float* op = outp + (((size_t)n * NCH + c0) * HP + y) * WP + x;

    // --- per-thread grid sample (once) ---
    const float v    = (y + 0.5f) * (1.0f / HP);
    const float invW = 1.0f / IMG_W, invH = 1.0f / IMG_H;

    float u = (x + 0.5f) * ((float)(NPTS - 1) / (float)WP);
    int i0 = (int)floorf(u);
    i0 = max(0, min(i0, NPTS - 2));
    float f = u - (float)i0;
    int j0 = 13 - i0, j1 = 12 - i0;

    float tx = (__ldg(pp + 2*i0)       * (1.0f - f) + __ldg(pp + 2*(i0+1))     * f) * invW;
    float ty = (__ldg(pp + 2*i0 + 1)   * (1.0f - f) + __ldg(pp + 2*(i0+1) + 1) * f) * invH;
    float bx = (__ldg(pp + 2*j0)       * (1.0f - f) + __ldg(pp + 2*j1)         * f) * invW;
    float by = (__ldg(pp + 2*j0 + 1)   * (1.0f - f) + __ldg(pp + 2*j1 + 1)     * f) * invH;

    float gx = tx * (1.0f - v) + bx * v;
    float gy = ty * (1.0f - v) + by * v;

    float xf = gx * (float)W - 0.5f;
    float yf = gy * (float)H - 0.5f;
    float x0f = floorf(xf), y0f = floorf(yf);
    float wx = xf - x0f, wy = yf - y0f;
    int x0 = (int)x0f, y0i = (int)y0f;
    int x1 = x0 + 1,   y1 = y0i + 1;

    int x0c = min(max(x0, 0), W - 1), x1c = min(max(x1, 0), W - 1);
    int y0c = min(max(y0i, 0), H - 1), y1c = min(max(y1, 0), H - 1);
    float m00 = ((x0 >= 0) & (x0 < W) & (y0i >= 0) & (y0i < H)) ? 1.0f : 0.0f;
    float m10 = ((x1 >= 0) & (x1 < W) & (y0i >= 0) & (y0i < H)) ? 1.0f : 0.0f;
    float m01 = ((x0 >= 0) & (x0 < W) & (y1 >= 0) & (y1 < H)) ? 1.0f : 0.0f;
    float m11 = ((x1 >= 0) & (x1 < W) & (y1 >= 0) & (y1 < H)) ? 1.0f : 0.0f;

    const float w00 = m00 * (1.0f - wx) * (1.0f - wy);
    const float w10 = m10 * wx          * (1.0f - wy);
    const float w01 = m01 * (1.0f - wx) * wy;
    const float w11 = m11 * wx          * wy;

    const int o00 = y0c * W + x0c;
    const int o10 = y0c * W + x1c;
    const int o01 = y1c * W + x0c;
    const int o11 = y1c * W + x1c;

    constexpr size_t OST = (size_t)HP * WP;   // output channel stride

    // --- channel stream, unrolled x8 for load batching ---
#pragma unroll 8
    for (int c = 0; c < CCHUNK; c++) {
        float v00 = __ldg(p + o00);
        float v10 = __ldg(p + o10);
        float v01 = __ldg(p + o01);
        float v11 = __ldg(p + o11);
        float r = v00 * w00 + v10 * w10 + v01 * w01 + v11 * w11;
        __stcs(op + (size_t)c * OST, r);
        p += HW;
    }
}

__global__ void __launch_bounds__(256, 5)
fused_pool_kernel(const float* __restrict__ f0, const float* __restrict__ f1,
                  const float* __restrict__ f2, const float* __restrict__ f3,
                  const float* __restrict__ polys, const int* __restrict__ img_ids,
                  const int* __restrict__ lens, float* __restrict__ out) {
    const int n = blockIdx.y;
    const float* pp = polys + (size_t)n * (2 * NPTS * 2);

    // --- per-thread uniform meta (broadcast __ldg; no smem, no barriers) ---
    float minx = __ldg(pp + 0), maxx = minx;
    float miny = __ldg(pp + 1), maxy = miny;
#pragma unroll
    for (int i = 1; i < 2 * NPTS; i++) {
        float px = __ldg(pp + 2 * i), py = __ldg(pp + 2 * i + 1);
        minx = fminf(minx, px); maxx = fmaxf(maxx, px);
        miny = fminf(miny, py); maxy = fmaxf(maxy, py);
    }
    float s  = sqrtf((maxx - minx) * (maxy - miny));
    float vv = 4.0f + log2f(s / 224.0f + 1e-6f);
    float fl = fminf(fmaxf(floorf(vv), 2.0f), 5.0f);
    const int s_lvl = (int)fl - 2;
    const int s_pid = (__ldg(lens + n) > 8) ? 1 : 0;
    const int s_img = __ldg(img_ids + n);

    constexpr int CHUNKS = NCH / CCHUNK;   // 8

    if (blockIdx.x < CHUNKS) {
        // Output 0: (N, C, 8, 32), pooler 0. 256 thr = 32 x * 8 y.
        pool_body<32, 0, 8>(blockIdx.x, 0, n, f0, f1, f2, f3,
                            out, pp, s_lvl, s_pid, s_img);
    } else {
        // Output 1: (N, C, 8, 64), pooler 1. 256 thr = 64 x * 4 y, 2 halves.
        const int idx = blockIdx.x - CHUNKS;
        float* out1 = out + (size_t)NROI * NCH * HP * 32;
        pool_body<64, 1, 4>(idx >> 1, idx & 1, n, f0, f1, f2, f3,
                            out1, pp, s_lvl, s_pid, s_img);
    }
}

extern "C" void kernel_launch(void* const* d_in, const int* in_sizes, int n_in,
                              void* d_out, int out_size) {
    const float* f0     = (const float*)d_in[0];
    const float* f1     = (const float*)d_in[1];
    const float* f2     = (const float*)d_in[2];
    const float* f3     = (const float*)d_in[3];
    const float* polys  = (const float*)d_in[4];
    const int*   imgids = (const int*)  d_in[5];
    const int*   lens   = (const int*)  d_in[6];
    float* out = (float*)d_out;

    const int N = in_sizes[4] / (2 * NPTS * 2);   // 256

    dim3 grid(3 * (NCH / CCHUNK), N);             // 24 x 256
    fused_pool_kernel<<<grid, 256>>>(f0, f1, f2, f3, polys, imgids, lens, out);
}